// round 2
// baseline (speedup 1.0000x reference)
#include <cuda_runtime.h>
#include <cuda_bf16.h>

// Problem constants (fixed shapes for this dataset)
#define N_NODES_MAX 50000
#define D 64

// Scratch (no device allocation allowed -> __device__ globals)
__device__ float g_agg[N_NODES_MAX * D];   // aggregated features [N, 64]
__device__ int   g_deg[N_NODES_MAX];       // out-degree per node

// ---------------------------------------------------------------------------
// Kernel 1: zero the scratch buffers
// ---------------------------------------------------------------------------
__global__ void zero_kernel(int n_nodes) {
    int i = blockIdx.x * blockDim.x + threadIdx.x;
    int stride = gridDim.x * blockDim.x;
    float4 z = make_float4(0.f, 0.f, 0.f, 0.f);
    float4* a4 = reinterpret_cast<float4*>(g_agg);
    int n4 = n_nodes * (D / 4);
    for (int k = i; k < n4; k += stride) a4[k] = z;
    for (int k = i; k < n_nodes; k += stride) g_deg[k] = 0;
}

// ---------------------------------------------------------------------------
// Kernel 2: edge-parallel scatter-sum + degree histogram
// 16 threads per edge; each thread moves one float4 (16B) via vector RED.
// ---------------------------------------------------------------------------
__global__ void __launch_bounds__(256) scatter_kernel(const float4* __restrict__ h4,
                                                      const int* __restrict__ src,
                                                      const int* __restrict__ dst,
                                                      int n_edges) {
    int gid = blockIdx.x * blockDim.x + threadIdx.x;
    int e = gid >> 4;           // edge id
    int c = gid & 15;           // float4 chunk within the 64-float row
    if (e >= n_edges) return;

    int s = src[e];
    int d = dst[e];

    if (c == 0) atomicAdd(&g_deg[s], 1);

    float4 v = h4[s * (D / 4) + c];
    float* addr = &g_agg[d * D + c * 4];
    asm volatile("red.global.add.v4.f32 [%0], {%1, %2, %3, %4};"
                 :: "l"(addr), "f"(v.x), "f"(v.y), "f"(v.z), "f"(v.w)
                 : "memory");
}

// ---------------------------------------------------------------------------
// Kernel 3: out = relu((agg @ W) * deg^-0.5 + bias)
// One warp per node. W (16KB) and bias staged in smem.
// Each lane computes output columns {lane, lane+32}.
// ---------------------------------------------------------------------------
__global__ void __launch_bounds__(256) out_kernel(const float* __restrict__ W,
                                                  const float* __restrict__ bias,
                                                  float* __restrict__ out,
                                                  int n_nodes) {
    __shared__ float Ws[D * D];
    __shared__ float bs[D];
    __shared__ float abuf[8][D];   // one 64-float row per warp

    int tid = threadIdx.x;
    for (int k = tid; k < D * D; k += blockDim.x) Ws[k] = W[k];
    if (tid < D) bs[tid] = bias[tid];
    __syncthreads();

    int warp = tid >> 5;
    int lane = tid & 31;
    int gw = blockIdx.x * 8 + warp;
    int nwarps = gridDim.x * 8;

    for (int node = gw; node < n_nodes; node += nwarps) {
        // warp-cooperative load of the agg row (2 floats per lane)
        float2 a = reinterpret_cast<const float2*>(g_agg)[node * (D / 2) + lane];
        abuf[warp][2 * lane]     = a.x;
        abuf[warp][2 * lane + 1] = a.y;
        __syncwarp();

        float acc0 = 0.f, acc1 = 0.f;
        #pragma unroll
        for (int k = 0; k < D; k++) {
            float av = abuf[warp][k];
            acc0 = fmaf(av, Ws[k * D + lane],      acc0);
            acc1 = fmaf(av, Ws[k * D + lane + 32], acc1);
        }

        float norm = rsqrtf((float)g_deg[node]);   // out-degree >= 1 (self loops)
        float o0 = fmaf(acc0, norm, bs[lane]);
        float o1 = fmaf(acc1, norm, bs[lane + 32]);
        out[node * D + lane]      = fmaxf(o0, 0.f);
        out[node * D + lane + 32] = fmaxf(o1, 0.f);
        __syncwarp();   // protect abuf before next iteration overwrites it
    }
}

// ---------------------------------------------------------------------------
// Launch: zero -> scatter -> epilogue (all graph-capturable)
// ---------------------------------------------------------------------------
extern "C" void kernel_launch(void* const* d_in, const int* in_sizes, int n_in,
                              void* d_out, int out_size) {
    const float* h      = (const float*)d_in[0];   // [N, 64]
    const float* W      = (const float*)d_in[1];   // [64, 64]
    const float* bias   = (const float*)d_in[2];   // [64]
    const int*   src    = (const int*)d_in[3];     // [E]
    const int*   dst    = (const int*)d_in[4];     // [E]
    float*       out    = (float*)d_out;           // [N, 64]

    int n_nodes = in_sizes[0] / D;
    if (n_nodes > N_NODES_MAX) n_nodes = N_NODES_MAX;
    int n_edges = in_sizes[3];

    // 1) zero scratch
    zero_kernel<<<512, 256>>>(n_nodes);

    // 2) scatter-sum: 16 threads per edge
    long long work = (long long)n_edges * 16;
    int blocks = (int)((work + 255) / 256);
    scatter_kernel<<<blocks, 256>>>(reinterpret_cast<const float4*>(h), src, dst, n_edges);

    // 3) GEMM + norm + bias + relu
    int wblocks = (n_nodes + 7) / 8;
    if (wblocks > 1184) wblocks = 1184;
    out_kernel<<<wblocks, 256>>>(W, bias, out, n_nodes);
}

// round 3
// speedup vs baseline: 1.2991x; 1.2991x over previous
#include <cuda_runtime.h>
#include <cuda_bf16.h>

#define N_NODES_MAX 50000
#define D 64
#define MAX_DEG 160

// __device__ scratch (no runtime allocation allowed)
__device__ float g_agg[N_NODES_MAX * D];          // overflow-fallback accumulator
__device__ int   g_deg[N_NODES_MAX];              // out-degree (over src) for norm
__device__ int   g_cnt[N_NODES_MAX];              // in-degree counter for buckets
__device__ int   g_bucket[N_NODES_MAX * MAX_DEG]; // src lists per dst

// ---------------------------------------------------------------------------
// Kernel 1: zero scratch
// ---------------------------------------------------------------------------
__global__ void zero_kernel(int n_nodes) {
    int i = blockIdx.x * blockDim.x + threadIdx.x;
    int stride = gridDim.x * blockDim.x;
    float4 z = make_float4(0.f, 0.f, 0.f, 0.f);
    float4* a4 = reinterpret_cast<float4*>(g_agg);
    int n4 = n_nodes * (D / 4);
    for (int k = i; k < n4; k += stride) a4[k] = z;
    for (int k = i; k < n_nodes; k += stride) { g_deg[k] = 0; g_cnt[k] = 0; }
}

// ---------------------------------------------------------------------------
// Kernel 2: build dst->src buckets + out-degree histogram (1 thread / edge)
// Overflow edges (never expected at MAX_DEG=160) fall back to direct RED
// into g_agg, which the gather kernel uses as its accumulator init.
// ---------------------------------------------------------------------------
__global__ void __launch_bounds__(256) build_kernel(const float4* __restrict__ h4,
                                                    const int* __restrict__ src,
                                                    const int* __restrict__ dst,
                                                    int n_edges) {
    int e = blockIdx.x * blockDim.x + threadIdx.x;
    if (e >= n_edges) return;
    int s = src[e];
    int d = dst[e];
    atomicAdd(&g_deg[s], 1);
    int pos = atomicAdd(&g_cnt[d], 1);
    if (pos < MAX_DEG) {
        g_bucket[d * MAX_DEG + pos] = s;
    } else {
        // guaranteed-correct fallback: scatter the row directly
        #pragma unroll
        for (int c = 0; c < D / 4; c++) {
            float4 v = h4[s * (D / 4) + c];
            float* addr = &g_agg[d * D + c * 4];
            asm volatile("red.global.add.v4.f32 [%0], {%1, %2, %3, %4};"
                         :: "l"(addr), "f"(v.x), "f"(v.y), "f"(v.z), "f"(v.w)
                         : "memory");
        }
    }
}

// ---------------------------------------------------------------------------
// Kernel 3 (fused): gather-aggregate + GEMM + norm + bias + relu
// One warp per node; each lane accumulates feature cols {2*lane, 2*lane+1}.
// ---------------------------------------------------------------------------
__global__ void __launch_bounds__(256) fused_kernel(const float2* __restrict__ h2,
                                                    const float* __restrict__ W,
                                                    const float* __restrict__ bias,
                                                    float* __restrict__ out,
                                                    int n_nodes) {
    __shared__ float  Ws[D * D];
    __shared__ float  bs[D];
    __shared__ float2 abuf[8][D / 2];   // one row per warp

    int tid = threadIdx.x;
    for (int k = tid; k < D * D; k += blockDim.x) Ws[k] = W[k];
    if (tid < D) bs[tid] = bias[tid];
    __syncthreads();

    int warp = tid >> 5;
    int lane = tid & 31;
    int gw = blockIdx.x * 8 + warp;
    int nwarps = gridDim.x * 8;

    for (int node = gw; node < n_nodes; node += nwarps) {
        int cnt = g_cnt[node];
        if (cnt > MAX_DEG) cnt = MAX_DEG;
        const int* lst = &g_bucket[node * MAX_DEG];

        // init from overflow-fallback accumulator (normally zeros)
        float2 acc = reinterpret_cast<const float2*>(g_agg)[node * (D / 2) + lane];

        int i = 0;
        for (; i + 4 <= cnt; i += 4) {
            int s0 = lst[i], s1 = lst[i + 1], s2 = lst[i + 2], s3 = lst[i + 3];
            float2 v0 = h2[s0 * (D / 2) + lane];
            float2 v1 = h2[s1 * (D / 2) + lane];
            float2 v2 = h2[s2 * (D / 2) + lane];
            float2 v3 = h2[s3 * (D / 2) + lane];
            acc.x += v0.x + v1.x + v2.x + v3.x;
            acc.y += v0.y + v1.y + v2.y + v3.y;
        }
        for (; i < cnt; i++) {
            int s = lst[i];
            float2 v = h2[s * (D / 2) + lane];
            acc.x += v.x;
            acc.y += v.y;
        }

        // broadcast row via smem, then 64x64 GEMM for this row
        abuf[warp][lane] = acc;
        __syncwarp();

        float acc0 = 0.f, acc1 = 0.f;
        const float* arow = reinterpret_cast<const float*>(abuf[warp]);
        #pragma unroll
        for (int k = 0; k < D; k++) {
            float av = arow[k];
            acc0 = fmaf(av, Ws[k * D + lane],      acc0);
            acc1 = fmaf(av, Ws[k * D + lane + 32], acc1);
        }

        float norm = rsqrtf((float)g_deg[node]);   // >= 1 via self loops
        float o0 = fmaf(acc0, norm, bs[lane]);
        float o1 = fmaf(acc1, norm, bs[lane + 32]);
        out[node * D + lane]      = fmaxf(o0, 0.f);
        out[node * D + lane + 32] = fmaxf(o1, 0.f);
        __syncwarp();   // protect abuf before next iteration
    }
}

// ---------------------------------------------------------------------------
extern "C" void kernel_launch(void* const* d_in, const int* in_sizes, int n_in,
                              void* d_out, int out_size) {
    const float* h    = (const float*)d_in[0];   // [N, 64]
    const float* W    = (const float*)d_in[1];   // [64, 64]
    const float* bias = (const float*)d_in[2];   // [64]
    const int*   src  = (const int*)d_in[3];     // [E]
    const int*   dst  = (const int*)d_in[4];     // [E]
    float*       out  = (float*)d_out;           // [N, 64]

    int n_nodes = in_sizes[0] / D;
    if (n_nodes > N_NODES_MAX) n_nodes = N_NODES_MAX;
    int n_edges = in_sizes[3];

    zero_kernel<<<512, 256>>>(n_nodes);

    int bblocks = (n_edges + 255) / 256;
    build_kernel<<<bblocks, 256>>>(reinterpret_cast<const float4*>(h), src, dst, n_edges);

    int fblocks = (n_nodes + 7) / 8;
    if (fblocks > 1184) fblocks = 1184;
    fused_kernel<<<fblocks, 256>>>(reinterpret_cast<const float2*>(h), W, bias, out, n_nodes);
}

// round 4
// speedup vs baseline: 1.3447x; 1.0351x over previous
#include <cuda_runtime.h>
#include <cuda_fp16.h>

#define N_NODES_MAX 50000
#define D 64
#define MAX_DEG 160

// __device__ scratch (no runtime allocation allowed)
__device__ __half2 g_h16[N_NODES_MAX * (D / 2)];   // fp16 copy of h [N,64]
__device__ int     g_deg[N_NODES_MAX];             // out-degree (src) for norm
__device__ int     g_cnt[N_NODES_MAX];             // in-degree counter
__device__ int     g_bucket[N_NODES_MAX * MAX_DEG];// src lists per dst

// ---------------------------------------------------------------------------
// Kernel 1: zero counters + convert h -> fp16
// ---------------------------------------------------------------------------
__global__ void __launch_bounds__(256) prep_kernel(const float2* __restrict__ h2,
                                                   int n_nodes) {
    int i = blockIdx.x * blockDim.x + threadIdx.x;
    int stride = gridDim.x * blockDim.x;
    int nelem = n_nodes * (D / 2);
    for (int k = i; k < nelem; k += stride) {
        float2 v = h2[k];
        g_h16[k] = __floats2half2_rn(v.x, v.y);
    }
    for (int k = i; k < n_nodes; k += stride) { g_deg[k] = 0; g_cnt[k] = 0; }
}

// ---------------------------------------------------------------------------
// Kernel 2: build dst->src buckets + out-degree histogram (1 thread / edge)
// Overflow (cnt > MAX_DEG) is handled exactly by a rescan in the fused kernel.
// ---------------------------------------------------------------------------
__global__ void __launch_bounds__(256) build_kernel(const int* __restrict__ src,
                                                    const int* __restrict__ dst,
                                                    int n_edges) {
    int e = blockIdx.x * blockDim.x + threadIdx.x;
    if (e >= n_edges) return;
    int s = src[e];
    int d = dst[e];
    atomicAdd(&g_deg[s], 1);
    int pos = atomicAdd(&g_cnt[d], 1);
    if (pos < MAX_DEG) g_bucket[d * MAX_DEG + pos] = s;
}

// ---------------------------------------------------------------------------
// Kernel 3 (fused): gather-aggregate (fp16 rows, fp32 acc) + GEMM + norm
//                   + bias + relu. One warp per node.
// ---------------------------------------------------------------------------
__global__ void __launch_bounds__(256) fused_kernel(const float* __restrict__ hfp32,
                                                    const float* __restrict__ W,
                                                    const float* __restrict__ bias,
                                                    const int* __restrict__ src,
                                                    const int* __restrict__ dst,
                                                    float* __restrict__ out,
                                                    int n_nodes, int n_edges) {
    __shared__ float  Ws[D * D];
    __shared__ float  bs[D];
    __shared__ float2 abuf[8][D / 2];

    int tid = threadIdx.x;
    for (int k = tid; k < D * D; k += blockDim.x) Ws[k] = W[k];
    if (tid < D) bs[tid] = bias[tid];
    __syncthreads();

    int warp = tid >> 5;
    int lane = tid & 31;
    int gw = blockIdx.x * 8 + warp;
    int nwarps = gridDim.x * 8;

    for (int node = gw; node < n_nodes; node += nwarps) {
        int cnt = g_cnt[node];
        float2 acc = make_float2(0.f, 0.f);

        if (cnt <= MAX_DEG) {
            const int* lst = &g_bucket[node * MAX_DEG];
            int i = 0;
            for (; i + 4 <= cnt; i += 4) {
                int s0 = lst[i], s1 = lst[i + 1], s2 = lst[i + 2], s3 = lst[i + 3];
                float2 v0 = __half22float2(g_h16[s0 * (D / 2) + lane]);
                float2 v1 = __half22float2(g_h16[s1 * (D / 2) + lane]);
                float2 v2 = __half22float2(g_h16[s2 * (D / 2) + lane]);
                float2 v3 = __half22float2(g_h16[s3 * (D / 2) + lane]);
                acc.x += (v0.x + v1.x) + (v2.x + v3.x);
                acc.y += (v0.y + v1.y) + (v2.y + v3.y);
            }
            for (; i < cnt; i++) {
                float2 v = __half22float2(g_h16[lst[i] * (D / 2) + lane]);
                acc.x += v.x;
                acc.y += v.y;
            }
        } else {
            // exact fallback (statistically never executes): scan all edges
            for (int e = 0; e < n_edges; e++) {
                if (dst[e] == node) {
                    int s = src[e];
                    float2 v = reinterpret_cast<const float2*>(hfp32)[s * (D / 2) + lane];
                    acc.x += v.x;
                    acc.y += v.y;
                }
            }
        }

        // broadcast row via smem, then 64x64 row GEMM
        abuf[warp][lane] = acc;
        __syncwarp();

        float acc0 = 0.f, acc1 = 0.f;
        const float* arow = reinterpret_cast<const float*>(abuf[warp]);
        #pragma unroll
        for (int k = 0; k < D; k++) {
            float av = arow[k];
            acc0 = fmaf(av, Ws[k * D + lane],      acc0);
            acc1 = fmaf(av, Ws[k * D + lane + 32], acc1);
        }

        float norm = rsqrtf((float)g_deg[node]);   // >= 1 via self loops
        float o0 = fmaf(acc0, norm, bs[lane]);
        float o1 = fmaf(acc1, norm, bs[lane + 32]);
        out[node * D + lane]      = fmaxf(o0, 0.f);
        out[node * D + lane + 32] = fmaxf(o1, 0.f);
        __syncwarp();
    }
}

// ---------------------------------------------------------------------------
extern "C" void kernel_launch(void* const* d_in, const int* in_sizes, int n_in,
                              void* d_out, int out_size) {
    const float* h    = (const float*)d_in[0];   // [N, 64]
    const float* W    = (const float*)d_in[1];   // [64, 64]
    const float* bias = (const float*)d_in[2];   // [64]
    const int*   src  = (const int*)d_in[3];     // [E]
    const int*   dst  = (const int*)d_in[4];     // [E]
    float*       out  = (float*)d_out;           // [N, 64]

    int n_nodes = in_sizes[0] / D;
    if (n_nodes > N_NODES_MAX) n_nodes = N_NODES_MAX;
    int n_edges = in_sizes[3];

    prep_kernel<<<2048, 256>>>(reinterpret_cast<const float2*>(h), n_nodes);

    int bblocks = (n_edges + 255) / 256;
    build_kernel<<<bblocks, 256>>>(src, dst, n_edges);

    int fblocks = (n_nodes + 7) / 8;
    fused_kernel<<<fblocks, 256>>>(h, W, bias, src, dst, out, n_nodes, n_edges);
}